// round 3
// baseline (speedup 1.0000x reference)
#include <cuda_runtime.h>
#include <math.h>

#define N_   2
#define C_   256
#define H_   96
#define W_   96
#define G_   4
#define P_   9
#define GC_  64
#define HW_  (H_*W_)        // 9216
#define NPIX (N_*HW_)       // 18432
#define OM_  108            // G*P*3
#define MCNT ((float)(C_*H_*W_))   // per-sample element count for GroupNorm(1,C)

// ---------------- device scratch (no allocation allowed) ----------------
__device__ float g_ctx [NPIX*C_];   // post-dwconv context, NHWC
__device__ float g_xt  [NPIX*C_];   // input x transposed to NHWC
__device__ float g_om  [NPIX*OM_];  // offset/mask head output
__device__ float g_omwT[C_*OM_];    // om_w transposed to [K=256][108]
__device__ float g_stats[4];        // sum0, sumsq0, sum1, sumsq1
__device__ float g_meanr[4];        // mean0, rstd0, mean1, rstd1

// ---------------- k0: zero stats + transpose om_w ----------------
__global__ void k0_init(const float* __restrict__ om_w) {
    int idx = blockIdx.x * 256 + threadIdx.x;
    if (idx < 4) g_stats[idx] = 0.f;
    if (idx < C_*OM_) {
        int j = idx % OM_;       // output row of om_w  [108,256]
        int k = idx / OM_;       // channel
        g_omwT[idx] = om_w[j*C_ + k];
    }
}

// ---------------- k1: depthwise conv + bias, NHWC transposes, GN stats ----------------
__global__ void k1_dwconv(const float* __restrict__ x,
                          const float* __restrict__ dw_w,
                          const float* __restrict__ dw_b) {
    __shared__ float s_ctx[32][33];
    __shared__ float s_x  [32][33];
    __shared__ float2 red[256];

    int tx = threadIdx.x, ty = threadIdx.y;
    int w     = blockIdx.x * 32 + tx;
    int cbase = blockIdx.y * 32;
    int z = blockIdx.z;
    int n = z / H_, h = z - n * H_;

    float lsum = 0.f, lsq = 0.f;
    #pragma unroll
    for (int i = 0; i < 4; i++) {
        int cl = ty + i*8;
        int c  = cbase + cl;
        const float* xc = x + (long)((n*C_ + c)*H_) * W_;
        float acc = dw_b[c];
        #pragma unroll
        for (int dy = 0; dy < 3; dy++) {
            int hh = h + dy - 1;
            if (hh < 0 || hh >= H_) continue;
            #pragma unroll
            for (int dx = 0; dx < 3; dx++) {
                int ww = w + dx - 1;
                if (ww < 0 || ww >= W_) continue;
                acc += xc[hh*W_ + ww] * dw_w[c*9 + dy*3 + dx];
            }
        }
        s_ctx[cl][tx] = acc;
        s_x  [cl][tx] = xc[h*W_ + w];
        lsum += acc; lsq += acc*acc;
    }
    __syncthreads();
    // transposed, coalesced-in-c writes (NHWC)
    #pragma unroll
    for (int i = 0; i < 4; i++) {
        int wl = ty + i*8;
        long addr = (long)((n*H_ + h)*W_ + blockIdx.x*32 + wl) * C_ + cbase + tx;
        g_ctx[addr] = s_ctx[tx][wl];
        g_xt [addr] = s_x  [tx][wl];
    }
    // block reduce stats
    int t = ty*32 + tx;
    red[t] = make_float2(lsum, lsq);
    __syncthreads();
    for (int s = 128; s > 0; s >>= 1) {
        if (t < s) { red[t].x += red[t+s].x; red[t].y += red[t+s].y; }
        __syncthreads();
    }
    if (t == 0) {
        atomicAdd(&g_stats[2*n],   red[0].x);
        atomicAdd(&g_stats[2*n+1], red[0].y);
    }
}

// ---------------- k2: finalize mean / rstd ----------------
__global__ void k2_finalize() {
    int t = threadIdx.x;
    if (t < 2) {
        float mu  = g_stats[2*t] / MCNT;
        float var = g_stats[2*t+1] / MCNT - mu*mu;
        g_meanr[2*t]   = mu;
        g_meanr[2*t+1] = rsqrtf(var + 1e-5f);
    }
}

// ---------------- k3: fused GN+GELU + GEMM  om = gelu(norm(ctx)) @ omw^T + b ----------------
// BM=128 pixels, BN=112 (108 padded), BK=32; 256 threads, 8x7 register tile.
__global__ void k3_gemm(const float* __restrict__ gn_w,
                        const float* __restrict__ gn_b,
                        const float* __restrict__ om_b) {
    __shared__ float As[32][133];   // [kk][pixel], pad 133 (gcd(133,32)=1)
    __shared__ float Bs[32][116];   // [kk][j],      pad 116

    int pb = blockIdx.x * 128;
    int n  = pb / HW_;              // tile never crosses samples (9216 % 128 == 0)
    float mu = g_meanr[2*n], rs = g_meanr[2*n+1];

    int tid = threadIdx.x;
    int tr = tid >> 4;              // 0..15  -> 8 pixels each
    int tc = tid & 15;              // 0..15  -> 7 outputs each

    float acc[8][7];
    #pragma unroll
    for (int m = 0; m < 8; m++)
        #pragma unroll
        for (int j = 0; j < 7; j++) acc[m][j] = 0.f;

    for (int k0 = 0; k0 < C_; k0 += 32) {
        // A tile: GN + exact GELU fused on load (each element touched once overall)
        #pragma unroll
        for (int it = 0; it < 16; it++) {
            int e  = tid + it*256;
            int i  = e >> 5;
            int kk = e & 31;
            int c  = k0 + kk;
            float v = g_ctx[(long)(pb + i)*C_ + c];
            v = (v - mu) * rs * gn_w[c] + gn_b[c];
            v = 0.5f * v * (1.f + erff(v * 0.70710678118654752f));
            As[kk][i] = v;
        }
        // B tile
        #pragma unroll
        for (int it = 0; it < 14; it++) {
            int e  = tid + it*256;
            int kk = e / 112;
            int j  = e - kk*112;
            Bs[kk][j] = (j < OM_) ? g_omwT[(k0 + kk)*OM_ + j] : 0.f;
        }
        __syncthreads();
        #pragma unroll
        for (int kk = 0; kk < 32; kk++) {
            float a[8], b[7];
            #pragma unroll
            for (int m = 0; m < 8; m++) a[m] = As[kk][tr*8 + m];
            #pragma unroll
            for (int j = 0; j < 7; j++) b[j] = Bs[kk][tc*7 + j];
            #pragma unroll
            for (int m = 0; m < 8; m++)
                #pragma unroll
                for (int j = 0; j < 7; j++) acc[m][j] += a[m] * b[j];
        }
        __syncthreads();
    }
    #pragma unroll
    for (int m = 0; m < 8; m++) {
        int row = pb + tr*8 + m;
        #pragma unroll
        for (int j = 0; j < 7; j++) {
            int col = tc*7 + j;
            if (col < OM_) g_om[(long)row*OM_ + col] = acc[m][j] + om_b[col];
        }
    }
}

// ---------------- k4: softmax*uncertainty + DCNv3 bilinear sampling + output ----------------
// One block = 8 consecutive-w pixels, 256 threads (thread = channel).
__global__ void k4_sample(const float* __restrict__ unc, float* __restrict__ out) {
    __shared__ float om_s[8][112];
    __shared__ float mmax[32], mscale[32];
    __shared__ int   offs[288][4];
    __shared__ float wts [288][4];

    int bid = blockIdx.x;
    int w0 = (bid % 12) * 8;
    int h  = (bid / 12) % H_;
    int n  = bid / (12 * H_);
    int pixbase = (n*H_ + h)*W_ + w0;
    int tid = threadIdx.x;

    for (int idx = tid; idx < 8*OM_; idx += 256) {
        int pix = idx / OM_, j = idx - pix*OM_;
        om_s[pix][j] = g_om[(long)(pixbase + pix)*OM_ + j];
    }
    __syncthreads();

    // softmax stats per (pix, g)
    if (tid < 32) {
        int pix = tid >> 2, g = tid & 3;
        const float* r = &om_s[pix][72 + g*9];
        float m = r[0];
        #pragma unroll
        for (int p = 1; p < 9; p++) m = fmaxf(m, r[p]);
        float s = 0.f;
        #pragma unroll
        for (int p = 0; p < 9; p++) s += expf(r[p] - m);
        float u = unc[pixbase + pix];
        mmax[tid]   = m;
        mscale[tid] = u / s;
    }
    __syncthreads();

    // tap params per (pix, g, p): 4 clamped base offsets + 4 mask-premultiplied weights
    for (int idx = tid; idx < 288; idx += 256) {
        int pix = idx / 36, gp = idx - pix*36;
        int g = gp / 9, p = gp - g*9;
        float offx = om_s[pix][gp*2];
        float offy = om_s[pix][gp*2 + 1];
        float mval = expf(om_s[pix][72 + gp] - mmax[pix*4 + g]) * mscale[pix*4 + g];
        // sampling position in original-image coords (padded-frame algebra folded in)
        float tx = (float)(w0 + pix + (p/3) - 1) + offx;   // x-major point ordering
        float ty = (float)(h + (p - (p/3)*3) - 1) + offy;
        float fx = floorf(tx), fy = floorf(ty);
        int x0i = (int)fx, y0i = (int)fy;
        float wx = tx - fx, wy = ty - fy;
        #pragma unroll
        for (int q = 0; q < 4; q++) {
            int cy = y0i + (q >> 1);
            int cx = x0i + (q & 1);
            bool valid = (cy >= 0) && (cy < H_) && (cx >= 0) && (cx < W_);
            int cyc = min(max(cy, 0), H_-1);
            int cxc = min(max(cx, 0), W_-1);
            offs[idx][q] = ((n*H_ + cyc)*W_ + cxc) * C_;
            float wq = ((q >> 1) ? wy : 1.f - wy) * ((q & 1) ? wx : 1.f - wx);
            wts[idx][q] = valid ? mval * wq : 0.f;
        }
    }
    __syncthreads();

    // gather + accumulate: thread = channel c, loop over the 8 pixels
    int c = tid;
    int gbase = (c >> 6) * 9;
    float res[8];
    #pragma unroll
    for (int pix = 0; pix < 8; pix++) {
        float acc = 0.f;
        int e0 = pix*36 + gbase;
        #pragma unroll
        for (int p = 0; p < 9; p++) {
            int e = e0 + p;
            acc += wts[e][0] * g_xt[offs[e][0] + c];
            acc += wts[e][1] * g_xt[offs[e][1] + c];
            acc += wts[e][2] * g_xt[offs[e][2] + c];
            acc += wts[e][3] * g_xt[offs[e][3] + c];
        }
        res[pix] = acc;
    }
    // NCHW output: 8 consecutive w per thread -> two aligned float4 stores
    long base = ((long)(n*C_ + c)*H_ + h)*W_ + w0;
    *reinterpret_cast<float4*>(out + base)     = make_float4(res[0], res[1], res[2], res[3]);
    *reinterpret_cast<float4*>(out + base + 4) = make_float4(res[4], res[5], res[6], res[7]);
}

// ---------------- launch ----------------
extern "C" void kernel_launch(void* const* d_in, const int* in_sizes, int n_in,
                              void* d_out, int out_size) {
    const float* x    = (const float*)d_in[0];
    const float* unc  = (const float*)d_in[1];
    const float* dw_w = (const float*)d_in[2];
    const float* dw_b = (const float*)d_in[3];
    const float* gn_w = (const float*)d_in[4];
    const float* gn_b = (const float*)d_in[5];
    const float* om_w = (const float*)d_in[6];
    const float* om_b = (const float*)d_in[7];
    float* out = (float*)d_out;

    k0_init   <<<112, 256>>>(om_w);
    k1_dwconv <<<dim3(3, 8, N_*H_), dim3(32, 8)>>>(x, dw_w, dw_b);
    k2_finalize<<<1, 32>>>();
    k3_gemm   <<<NPIX/128, 256>>>(gn_w, gn_b, om_b);
    k4_sample <<<NPIX/8, 256>>>(unc, out);
}

// round 5
// speedup vs baseline: 1.0749x; 1.0749x over previous
#include <cuda_runtime.h>
#include <math.h>

#define N_   2
#define C_   256
#define H_   96
#define W_   96
#define G_   4
#define P_   9
#define GC_  64
#define HW_  (H_*W_)        // 9216
#define NPIX (N_*HW_)       // 18432
#define OM_  108            // G*P*3
#define MCNT ((float)(C_*H_*W_))

// ---------------- device scratch ----------------
__device__ float g_ctx [NPIX*C_];   // post-dwconv context, NHWC (then GELU'd in place)
__device__ float g_xt  [NPIX*C_];   // input x transposed to NHWC
__device__ float g_om  [NPIX*OM_];  // offset/mask head output
__device__ float g_omwT[C_*OM_];    // om_w transposed to [K=256][108]
__device__ float g_stats[4];
__device__ float g_meanr[4];

__device__ __forceinline__ void ffma2(unsigned long long &acc,
                                      unsigned long long a,
                                      unsigned long long b) {
    asm volatile("fma.rn.f32x2 %0, %1, %2, %0;" : "+l"(acc) : "l"(a), "l"(b));
}

// ---------------- k0: zero stats + transpose om_w ----------------
__global__ void k0_init(const float* __restrict__ om_w) {
    int idx = blockIdx.x * 256 + threadIdx.x;
    if (idx < 4) g_stats[idx] = 0.f;
    if (idx < C_*OM_) {
        int j = idx % OM_;
        int k = idx / OM_;
        g_omwT[idx] = om_w[j*C_ + k];
    }
}

// ---------------- k1: depthwise conv + bias, NHWC transposes, GN stats ----------------
__global__ void k1_dwconv(const float* __restrict__ x,
                          const float* __restrict__ dw_w,
                          const float* __restrict__ dw_b) {
    __shared__ float s_ctx[32][33];
    __shared__ float s_x  [32][33];
    __shared__ float2 red[256];

    int tx = threadIdx.x, ty = threadIdx.y;
    int w     = blockIdx.x * 32 + tx;
    int cbase = blockIdx.y * 32;
    int z = blockIdx.z;
    int n = z / H_, h = z - n * H_;

    float lsum = 0.f, lsq = 0.f;
    #pragma unroll
    for (int i = 0; i < 4; i++) {
        int cl = ty + i*8;
        int c  = cbase + cl;
        const float* xc = x + (long)((n*C_ + c)*H_) * W_;
        float acc = dw_b[c];
        #pragma unroll
        for (int dy = 0; dy < 3; dy++) {
            int hh = h + dy - 1;
            if (hh < 0 || hh >= H_) continue;
            #pragma unroll
            for (int dx = 0; dx < 3; dx++) {
                int ww = w + dx - 1;
                if (ww < 0 || ww >= W_) continue;
                acc += xc[hh*W_ + ww] * dw_w[c*9 + dy*3 + dx];
            }
        }
        s_ctx[cl][tx] = acc;
        s_x  [cl][tx] = xc[h*W_ + w];
        lsum += acc; lsq += acc*acc;
    }
    __syncthreads();
    #pragma unroll
    for (int i = 0; i < 4; i++) {
        int wl = ty + i*8;
        long addr = (long)((n*H_ + h)*W_ + blockIdx.x*32 + wl) * C_ + cbase + tx;
        g_ctx[addr] = s_ctx[tx][wl];
        g_xt [addr] = s_x  [tx][wl];
    }
    int t = ty*32 + tx;
    red[t] = make_float2(lsum, lsq);
    __syncthreads();
    for (int s = 128; s > 0; s >>= 1) {
        if (t < s) { red[t].x += red[t+s].x; red[t].y += red[t+s].y; }
        __syncthreads();
    }
    if (t == 0) {
        atomicAdd(&g_stats[2*n],   red[0].x);
        atomicAdd(&g_stats[2*n+1], red[0].y);
    }
}

// ---------------- k2: finalize mean / rstd ----------------
__global__ void k2_finalize() {
    int t = threadIdx.x;
    if (t < 2) {
        float mu  = g_stats[2*t] / MCNT;
        float var = g_stats[2*t+1] / MCNT - mu*mu;
        g_meanr[2*t]   = mu;
        g_meanr[2*t+1] = rsqrtf(var + 1e-5f);
    }
}

// ---------------- k2b: GN + exact GELU elementwise on g_ctx (in place, float4) ----------------
__global__ void k2b_gelu(const float* __restrict__ gn_w,
                         const float* __restrict__ gn_b) {
    int i4 = blockIdx.x * 256 + threadIdx.x;        // one float4 per thread
    const int PER_N = HW_*C_/4;                      // 589824
    int n = (i4 >= PER_N) ? 1 : 0;
    float mu = g_meanr[2*n], rs = g_meanr[2*n+1];
    int cb = (i4*4) & (C_-1);
    float4 v = *reinterpret_cast<float4*>(&g_ctx[(long)i4*4]);
    float4 gw = *reinterpret_cast<const float4*>(&gn_w[cb]);
    float4 gb = *reinterpret_cast<const float4*>(&gn_b[cb]);
    float a0 = (v.x - mu)*rs*gw.x + gb.x;
    float a1 = (v.y - mu)*rs*gw.y + gb.y;
    float a2 = (v.z - mu)*rs*gw.z + gb.z;
    float a3 = (v.w - mu)*rs*gw.w + gb.w;
    const float s = 0.70710678118654752f;
    v.x = 0.5f*a0*(1.f + erff(a0*s));
    v.y = 0.5f*a1*(1.f + erff(a1*s));
    v.z = 0.5f*a2*(1.f + erff(a2*s));
    v.w = 0.5f*a3*(1.f + erff(a3*s));
    *reinterpret_cast<float4*>(&g_ctx[(long)i4*4]) = v;
}

// ---------------- k3: GEMM  g_om = g_ctx(gelu'd) @ omw^T + b  with packed f32x2 FMA ----------------
// BM=64, BN=112(108 padded), BK=32, 128 threads, 8x8 thread tile (tc<14 active).
__global__ void __launch_bounds__(128) k3_gemm(const float* __restrict__ om_b) {
    __shared__ float  As[32][68];     // [kk][pixel], pad 68 (even, /4-aligned reads)
    __shared__ float2 Bs[32][114];    // duplicated (v,v), j-major interleaved layout

    int tid = threadIdx.x;
    int pb  = blockIdx.x * 64;
    int tr  = tid >> 4;               // 0..7  -> pixels tr*8 .. tr*8+7
    int tc  = tid & 15;               // 0..15 -> cols tc*8 .. tc*8+7 (tc<14 real)
    bool active = tc < 14;
    int tcc = active ? tc : 0;

    unsigned long long acc[4][8];
    #pragma unroll
    for (int m = 0; m < 4; m++)
        #pragma unroll
        for (int j = 0; j < 8; j++) acc[m][j] = 0ull;

    for (int k0 = 0; k0 < C_; k0 += 32) {
        // A tile: 64x32, coalesced along kk
        #pragma unroll
        for (int it = 0; it < 16; it++) {
            int e  = tid + it*128;
            int i  = e >> 5;
            int kk = e & 31;
            As[kk][i] = g_ctx[(long)(pb + i)*C_ + k0 + kk];
        }
        // B tile: 112x32, duplicated pairs, position (col&7)*14 + (col>>3)
        #pragma unroll
        for (int it = 0; it < 28; it++) {
            int e  = tid + it*128;
            int kk = e / 112;
            int j  = e - kk*112;
            float v = (j < OM_) ? g_omwT[(k0 + kk)*OM_ + j] : 0.f;
            Bs[kk][(j & 7)*14 + (j >> 3)] = make_float2(v, v);
        }
        __syncthreads();
        #pragma unroll
        for (int kk = 0; kk < 32; kk++) {
            unsigned long long a[4], b[8];
            #pragma unroll
            for (int m = 0; m < 4; m++)
                a[m] = *reinterpret_cast<const unsigned long long*>(&As[kk][tr*8 + 2*m]);
            #pragma unroll
            for (int j = 0; j < 8; j++)
                b[j] = *reinterpret_cast<const unsigned long long*>(&Bs[kk][j*14 + tcc]);
            #pragma unroll
            for (int m = 0; m < 4; m++)
                #pragma unroll
                for (int j = 0; j < 8; j++) ffma2(acc[m][j], a[m], b[j]);
        }
        __syncthreads();
    }

    if (active) {
        #pragma unroll
        for (int j = 0; j < 8; j++) {
            int col = tc*8 + j;
            if (col < OM_) {
                float bb = om_b[col];
                #pragma unroll
                for (int m = 0; m < 4; m++) {
                    unsigned long long v = acc[m][j];
                    float lo = __uint_as_float((unsigned)(v & 0xffffffffu));
                    float hi = __uint_as_float((unsigned)(v >> 32));
                    int row0 = pb + tr*8 + 2*m;
                    g_om[(long)row0*OM_ + col]     = lo + bb;
                    g_om[(long)(row0+1)*OM_ + col] = hi + bb;
                }
            }
        }
    }
}

// ---------------- k4: softmax*uncertainty + DCNv3 sampling, float4 channels ----------------
// One block = 32 consecutive-w pixels, 256 threads.
// thread: 4 channels (c4 = (t&63)*4), 8 consecutive pixels (quarter = t>>6).
__global__ void k4_sample(const float* __restrict__ unc, float* __restrict__ out) {
    __shared__ float om_s[32][112];
    __shared__ float mmax[128], mscale[128];
    __shared__ int   offs[1152][4];
    __shared__ float wts [1152][4];

    int bid = blockIdx.x;
    int w0 = (bid % 3) * 32;
    int h  = (bid / 3) % H_;
    int n  = bid / (3 * H_);
    int pixbase = (n*H_ + h)*W_ + w0;
    int tid = threadIdx.x;

    for (int idx = tid; idx < 32*OM_; idx += 256) {
        int pix = idx / OM_, j = idx - pix*OM_;
        om_s[pix][j] = g_om[(long)(pixbase + pix)*OM_ + j];
    }
    __syncthreads();

    // softmax stats per (pix, g) : 128 pairs
    if (tid < 128) {
        int pix = tid >> 2, g = tid & 3;
        const float* r = &om_s[pix][72 + g*9];
        float m = r[0];
        #pragma unroll
        for (int p = 1; p < 9; p++) m = fmaxf(m, r[p]);
        float s = 0.f;
        #pragma unroll
        for (int p = 0; p < 9; p++) s += expf(r[p] - m);
        float u = unc[pixbase + pix];
        mmax[tid]   = m;
        mscale[tid] = u / s;
    }
    __syncthreads();

    // tap params per (pix, g, p): 1152 entries
    for (int idx = tid; idx < 1152; idx += 256) {
        int pix = idx / 36, gp = idx - pix*36;
        int g = gp / 9, p = gp - g*9;
        float offx = om_s[pix][gp*2];
        float offy = om_s[pix][gp*2 + 1];
        float mval = expf(om_s[pix][72 + gp] - mmax[pix*4 + g]) * mscale[pix*4 + g];
        float tx = (float)(w0 + pix + (p/3) - 1) + offx;   // x-major point ordering
        float ty = (float)(h + (p - (p/3)*3) - 1) + offy;
        float fx = floorf(tx), fy = floorf(ty);
        int x0i = (int)fx, y0i = (int)fy;
        float wx = tx - fx, wy = ty - fy;
        #pragma unroll
        for (int q = 0; q < 4; q++) {
            int cy = y0i + (q >> 1);
            int cx = x0i + (q & 1);
            bool valid = (cy >= 0) && (cy < H_) && (cx >= 0) && (cx < W_);
            int cyc = min(max(cy, 0), H_-1);
            int cxc = min(max(cx, 0), W_-1);
            offs[idx][q] = ((n*H_ + cyc)*W_ + cxc) * C_;
            float wq = ((q >> 1) ? wy : 1.f - wy) * ((q & 1) ? wx : 1.f - wx);
            wts[idx][q] = valid ? mval * wq : 0.f;
        }
    }
    __syncthreads();

    int c4      = (tid & 63) * 4;
    int quarter = tid >> 6;               // 0..3 -> pixels quarter*8 .. +7
    int gbase   = (c4 >> 6) * 9;
    float4 res[8];

    #pragma unroll
    for (int k = 0; k < 8; k++) {
        int pix = quarter*8 + k;
        float4 acc = make_float4(0.f, 0.f, 0.f, 0.f);
        int e0 = pix*36 + gbase;
        #pragma unroll
        for (int p = 0; p < 9; p++) {
            int e = e0 + p;
            #pragma unroll
            for (int q = 0; q < 4; q++) {
                float wq = wts[e][q];
                const float4 v = *reinterpret_cast<const float4*>(&g_xt[offs[e][q] + c4]);
                acc.x += wq * v.x; acc.y += wq * v.y;
                acc.z += wq * v.z; acc.w += wq * v.w;
            }
        }
        res[k] = acc;
    }

    // NCHW output: per channel, 8 consecutive w -> two float4 stores
    #pragma unroll
    for (int u = 0; u < 4; u++) {
        int c = c4 + u;
        long base = ((long)(n*C_ + c)*H_ + h)*W_ + w0 + quarter*8;
        float e0 = (&res[0].x)[u], e1 = (&res[1].x)[u], e2 = (&res[2].x)[u], e3 = (&res[3].x)[u];
        float e4 = (&res[4].x)[u], e5 = (&res[5].x)[u], e6 = (&res[6].x)[u], e7 = (&res[7].x)[u];
        *reinterpret_cast<float4*>(out + base)     = make_float4(e0, e1, e2, e3);
        *reinterpret_cast<float4*>(out + base + 4) = make_float4(e4, e5, e6, e7);
    }
}

// ---------------- launch ----------------
extern "C" void kernel_launch(void* const* d_in, const int* in_sizes, int n_in,
                              void* d_out, int out_size) {
    const float* x    = (const float*)d_in[0];
    const float* unc  = (const float*)d_in[1];
    const float* dw_w = (const float*)d_in[2];
    const float* dw_b = (const float*)d_in[3];
    const float* gn_w = (const float*)d_in[4];
    const float* gn_b = (const float*)d_in[5];
    const float* om_w = (const float*)d_in[6];
    const float* om_b = (const float*)d_in[7];
    float* out = (float*)d_out;

    k0_init   <<<112, 256>>>(om_w);
    k1_dwconv <<<dim3(3, 8, N_*H_), dim3(32, 8)>>>(x, dw_w, dw_b);
    k2_finalize<<<1, 32>>>();
    k2b_gelu  <<<NPIX*C_/4/256, 256>>>(gn_w, gn_b);
    k3_gemm   <<<NPIX/64, 128>>>(om_b);
    k4_sample <<<NPIX/32, 256>>>(unc, out);
}